// round 1
// baseline (speedup 1.0000x reference)
#include <cuda_runtime.h>
#include <cooperative_groups.h>

namespace cg = cooperative_groups;

#define NANCH 25200
#define BATCH 8
#define NEGF  (-1e9f)

#define CSIZE   8
#define PER_CTA (NANCH / CSIZE)   // 3150
#define TPB     256
#define KMAX    13                // ceil(3150/256)
#define NWARPS  (TPB / 32)

// Scratch (static __device__ — no allocation allowed)
__device__ float4 g_box[BATCH * NANCH];
__device__ float  g_area[BATCH * NANCH];
__device__ float  g_score[BATCH * NANCH];

// ---------------------------------------------------------------------------
// Stage 1: class argmax, score mask, box/area gather. Also zero-fills d_out.
// ---------------------------------------------------------------------------
__global__ void prep_kernel(const float* __restrict__ b20, const float* __restrict__ p20, const float* __restrict__ c20,
                            const float* __restrict__ b40, const float* __restrict__ p40, const float* __restrict__ c40,
                            const float* __restrict__ b80, const float* __restrict__ p80, const float* __restrict__ c80,
                            float* __restrict__ out, int out_size)
{
    int gid = blockIdx.x * blockDim.x + threadIdx.x;
    if (gid < out_size) out[gid] = 0.0f;
    if (gid >= BATCH * NANCH) return;

    int b = gid / NANCH;
    int j = gid - b * NANCH;

    const float *bb, *pp, *cc;
    int off;
    if (j < 1200)      { bb = b20; pp = p20; cc = c20; off = b * 1200  + j; }
    else if (j < 6000) { bb = b40; pp = p40; cc = c40; off = b * 4800  + (j - 1200); }
    else               { bb = b80; pp = p80; cc = c80; off = b * 19200 + (j - 6000); }

    float4 box = reinterpret_cast<const float4*>(bb)[off];
    const float4* crow = reinterpret_cast<const float4*>(cc) + off * 20;

    float best = __int_as_float(0xff800000); // -inf
    int bi = 0;
    #pragma unroll
    for (int q = 0; q < 20; q++) {
        float4 v = crow[q];
        if (v.x > best) { best = v.x; bi = 4 * q + 0; }
        if (v.y > best) { best = v.y; bi = 4 * q + 1; }
        if (v.z > best) { best = v.z; bi = 4 * q + 2; }
        if (v.w > best) { best = v.w; bi = 4 * q + 3; }
    }
    float p = pp[off];
    float s = __fmul_rn(p, (float)bi);       // score = p * argmax_class (as float)
    s = (s > 0.25f) ? s : NEGF;              // SCORE_THR mask

    g_box[gid]   = box;
    g_area[gid]  = __fmul_rn(__fsub_rn(box.z, box.x), __fsub_rn(box.w, box.y));
    g_score[gid] = s;
}

// Ordered-float bijection (monotonic u32 keys)
__device__ __forceinline__ unsigned int ford(float f) {
    unsigned int u = __float_as_uint(f);
    return u ^ ((unsigned int)(((int)u) >> 31) | 0x80000000u);
}
__device__ __forceinline__ float fuord(unsigned int o) {
    unsigned int u = (o & 0x80000000u) ? (o ^ 0x80000000u) : ~o;
    return __uint_as_float(u);
}

// ---------------------------------------------------------------------------
// Stage 2: sequential NMS. One 8-CTA cluster per batch; all per-anchor state
// lives in registers. One cluster.sync per iteration; candidates exchanged
// through double-buffered DSMEM slots.
// ---------------------------------------------------------------------------
__global__ void __cluster_dims__(CSIZE, 1, 1) __launch_bounds__(TPB, 1)
nms_kernel(float* __restrict__ out, int out_size)
{
    cg::cluster_group cluster = cg::this_cluster();
    extern __shared__ unsigned char smem_raw[];
    float4* sbox = reinterpret_cast<float4*>(smem_raw);                                       // PER_CTA float4
    unsigned long long* wbest = reinterpret_cast<unsigned long long*>(smem_raw + PER_CTA * 16); // NWARPS
    unsigned long long* slots = wbest + NWARPS;                                               // 2 parities x 4 u64

    const int t    = threadIdx.x;
    const int wid  = t >> 5;
    const int lane = t & 31;
    const int batch = blockIdx.x >> 3;
    const int rank  = blockIdx.x & 7;
    const int base  = rank * PER_CTA;   // batch-local anchor offset of this CTA

    float sc[KMAX], y1[KMAX], x1[KMAX], y2[KMAX], x2[KMAX], ar[KMAX];

    #pragma unroll
    for (int k = 0; k < KMAX; k++) {
        int l = k * TPB + t;
        if (l < PER_CTA) {
            int g = batch * NANCH + base + l;
            float4 bx = g_box[g];
            y1[k] = bx.x; x1[k] = bx.y; y2[k] = bx.z; x2[k] = bx.w;
            ar[k] = g_area[g];
            sc[k] = g_score[g];
            sbox[l] = bx;
        }
    }

    // Initial local argmax (ordered key; in-thread ties keep smallest k == smallest idx)
    unsigned int bord = 0; int bk = 0;
    #pragma unroll
    for (int k = 0; k < KMAX; k++) {
        int l = k * TPB + t;
        if (l < PER_CTA) {
            unsigned int o = ford(sc[k]);
            if (o > bord) { bord = o; bk = k; }
        }
    }
    __syncthreads();   // sbox visible to warp0's winner-box fetch

    int cnt = 0;
    const unsigned long long FULL = 0xFFFFFFFFull;

    for (int it = 0; it < 100; ++it) {
        // --- CTA-level argmax: key = (ord(score) << 32) | ~batch_local_idx ---
        int j = base + bk * TPB + t;
        unsigned long long key = ((unsigned long long)bord << 32) | (unsigned int)(~(unsigned int)j);
        #pragma unroll
        for (int o = 16; o > 0; o >>= 1) {
            unsigned long long other = __shfl_xor_sync((unsigned)FULL, key, o);
            if (other > key) key = other;
        }
        if (lane == 0) wbest[wid] = key;
        __syncthreads();

        unsigned long long* slot = slots + (it & 1) * 4;
        if (wid == 0) {
            unsigned long long kk = (lane < NWARPS) ? wbest[lane] : 0ull;
            #pragma unroll
            for (int o = 4; o > 0; o >>= 1) {
                unsigned long long other = __shfl_xor_sync((unsigned)FULL, kk, o);
                if (other > kk) kk = other;
            }
            if (lane == 0) {
                int wj = (int)(~(unsigned int)kk);   // batch-local idx (always in this CTA)
                float4 bx = sbox[wj - base];
                slot[0] = kk;
                slot[1] = ((unsigned long long)__float_as_uint(bx.y) << 32) | __float_as_uint(bx.x);
                slot[2] = ((unsigned long long)__float_as_uint(bx.w) << 32) | __float_as_uint(bx.z);
            }
        }
        cluster.sync();

        // --- Cluster-level winner: lanes 0-7 read peer candidate slots (DSMEM) ---
        unsigned long long pk = 0, pb1 = 0, pb2 = 0;
        if (lane < CSIZE) {
            unsigned long long* rs = cluster.map_shared_rank(slot, lane);
            pk = rs[0]; pb1 = rs[1]; pb2 = rs[2];
        }
        unsigned long long wk = pk;
        #pragma unroll
        for (int o = 16; o > 0; o >>= 1) {
            unsigned long long other = __shfl_xor_sync((unsigned)FULL, wk, o);
            if (other > wk) wk = other;
        }
        unsigned int bal = __ballot_sync((unsigned)FULL, (lane < CSIZE) && (pk == wk));
        int wl = __ffs(bal) - 1;
        unsigned long long wb1 = __shfl_sync((unsigned)FULL, pb1, wl);
        unsigned long long wb2 = __shfl_sync((unsigned)FULL, pb2, wl);
        float wy1 = __uint_as_float((unsigned int)wb1);
        float wx1 = __uint_as_float((unsigned int)(wb1 >> 32));
        float wy2 = __uint_as_float((unsigned int)wb2);
        float wx2 = __uint_as_float((unsigned int)(wb2 >> 32));
        int   wj  = (int)(~(unsigned int)wk);
        unsigned int whi = (unsigned int)(wk >> 32);
        float ws = fuord(whi);
        bool valid = ws > -5.0e8f;   // NEG * 0.5

        if (rank == 0 && t == 0) {
            int ob = (batch * 100 + it) * 6;
            if (ob + 5 < out_size) {
                if (valid) {
                    out[ob + 0] = fminf(fmaxf(wy1, 0.0f), 1.0f);
                    out[ob + 1] = fminf(fmaxf(wx1, 0.0f), 1.0f);
                    out[ob + 2] = fminf(fmaxf(wy2, 0.0f), 1.0f);
                    out[ob + 3] = fminf(fmaxf(wx2, 0.0f), 1.0f);
                    out[ob + 4] = ws;
                    out[ob + 5] = 0.0f;
                }
                // invalid rows stay pre-zeroed
            }
            if (valid) cnt++;
        }
        if (!valid) break;   // uniform across cluster: max stays NEG forever; rows pre-zeroed

        // --- Suppress + fused next local argmax (all register-resident) ---
        float warea = __fmul_rn(__fsub_rn(wy2, wy1), __fsub_rn(wx2, wx1));
        int rsel = wj - (base + t);   // == k*TPB iff self-hit in this thread
        bord = 0; bk = 0;
        bool need = false;
        float inter_s[KMAX], uni_s[KMAX];

        #pragma unroll
        for (int k = 0; k < KMAX; k++) {
            int l = k * TPB + t;
            if (l < PER_CTA) {
                float ih = fmaxf(__fsub_rn(fminf(wy2, y2[k]), fmaxf(wy1, y1[k])), 0.0f);
                float iw = fmaxf(__fsub_rn(fminf(wx2, x2[k]), fmaxf(wx1, x1[k])), 0.0f);
                float inter = __fmul_rn(ih, iw);
                float uni   = __fsub_rn(__fadd_rn(warea, ar[k]), inter);
                inter_s[k] = inter; uni_s[k] = uni;
                float i2  = __fadd_rn(inter, inter);
                bool upos = uni > 0.0f;
                // thr = RN(uni*(1+2^-22)) — strictly above the 0.5+2^-25 div midpoint
                float thr = __fmaf_rn(uni, 2.384185791015625e-7f, uni);
                bool fast_t = upos && (i2 >= thr);
                need = need || (upos && (i2 > uni) && (i2 < thr));
                bool supp = fast_t || (rsel == k * TPB);
                sc[k] = supp ? NEGF : sc[k];
                unsigned int o = ford(sc[k]);
                if (o > bord) { bord = o; bk = k; }
            }
        }
        if (need) {
            // Exact-division path for the (astronomically rare) ambiguous band.
            bord = 0; bk = 0;
            #pragma unroll
            for (int k = 0; k < KMAX; k++) {
                int l = k * TPB + t;
                if (l < PER_CTA) {
                    float uni = uni_s[k];
                    bool cond = false;
                    if (uni > 0.0f) cond = __fdiv_rn(inter_s[k], uni) > 0.5f;
                    bool supp = cond || (rsel == k * TPB);
                    sc[k] = supp ? NEGF : sc[k];
                    unsigned int o = ford(sc[k]);
                    if (o > bord) { bord = o; bk = k; }
                }
            }
        }
    }

    if (rank == 0 && t == 0) {
        int vi = BATCH * 100 * 6 + batch;   // valid counts after flattened pred
        if (vi < out_size) out[vi] = (float)cnt;
    }
    cluster.sync();   // no CTA may exit while peers might still read its DSMEM
}

// ---------------------------------------------------------------------------
extern "C" void kernel_launch(void* const* d_in, const int* in_sizes, int n_in,
                              void* d_out, int out_size)
{
    const float* b20 = (const float*)d_in[0];
    const float* p20 = (const float*)d_in[1];
    const float* c20 = (const float*)d_in[2];
    const float* b40 = (const float*)d_in[3];
    const float* p40 = (const float*)d_in[4];
    const float* c40 = (const float*)d_in[5];
    const float* b80 = (const float*)d_in[6];
    const float* p80 = (const float*)d_in[7];
    const float* c80 = (const float*)d_in[8];
    float* out = (float*)d_out;

    int total = BATCH * NANCH;
    int blocks = (total + TPB - 1) / TPB;
    prep_kernel<<<blocks, TPB>>>(b20, p20, c20, b40, p40, c40, b80, p80, c80, out, out_size);

    const int smem_bytes = PER_CTA * 16 + NWARPS * 8 + 8 * 8;   // sbox + wbest + slots
    cudaFuncSetAttribute(nms_kernel, cudaFuncAttributeMaxDynamicSharedMemorySize, smem_bytes);
    nms_kernel<<<BATCH * CSIZE, TPB, smem_bytes>>>(out, out_size);
}

// round 5
// speedup vs baseline: 1.0248x; 1.0248x over previous
#include <cuda_runtime.h>
#include <cooperative_groups.h>

namespace cg = cooperative_groups;

#define NANCH 25200
#define BATCH 8
#define NEGF  (-1e9f)

#define CSIZE   8
#define PER_CTA (NANCH / CSIZE)   // 3150
#define TPB     256
#define KMAX    13                // ceil(3150/256)
#define NWARP   8                 // warps per CTA
#define GWARPS  (CSIZE * NWARP)   // 64 warps per cluster

// ord(NEGF) = ~bits(-1e9f) = 0x319194D7
#define ORDNEG 0x319194D7u
#define FULLM  0xFFFFFFFFu

// smem layout (bytes)
#define SBOX_OFF  0                      // float4[PER_CTA] = 50400
#define SLOT_OFF  50432                  // u64 slots [2][64][4] (32B stride) = 4096
#define WIN_OFF   54528                  // winner [2][4 u64] = 64
#define BAR_OFF   54592                  // gather[2] @ +0,+8 ; bcast[2] @ +16,+24
#define SMEM_TOT  54656

// Scratch (static __device__ — no allocation allowed)
__device__ float4 g_box[BATCH * NANCH];
__device__ float  g_area[BATCH * NANCH];
__device__ float  g_score[BATCH * NANCH];

// ---------------------------------------------------------------------------
// Stage 1: class argmax, score mask, box/area gather. Also zero-fills d_out.
// ---------------------------------------------------------------------------
__global__ void prep_kernel(const float* __restrict__ b20, const float* __restrict__ p20, const float* __restrict__ c20,
                            const float* __restrict__ b40, const float* __restrict__ p40, const float* __restrict__ c40,
                            const float* __restrict__ b80, const float* __restrict__ p80, const float* __restrict__ c80,
                            float* __restrict__ out, int out_size)
{
    int gid = blockIdx.x * blockDim.x + threadIdx.x;
    if (gid < out_size) out[gid] = 0.0f;
    if (gid >= BATCH * NANCH) return;

    int b = gid / NANCH;
    int j = gid - b * NANCH;

    const float *bb, *pp, *cc;
    int off;
    if (j < 1200)      { bb = b20; pp = p20; cc = c20; off = b * 1200  + j; }
    else if (j < 6000) { bb = b40; pp = p40; cc = c40; off = b * 4800  + (j - 1200); }
    else               { bb = b80; pp = p80; cc = c80; off = b * 19200 + (j - 6000); }

    float4 box = reinterpret_cast<const float4*>(bb)[off];
    const float4* crow = reinterpret_cast<const float4*>(cc) + off * 20;

    float best = __int_as_float(0xff800000); // -inf
    int bi = 0;
    #pragma unroll
    for (int q = 0; q < 20; q++) {
        float4 v = crow[q];
        if (v.x > best) { best = v.x; bi = 4 * q + 0; }
        if (v.y > best) { best = v.y; bi = 4 * q + 1; }
        if (v.z > best) { best = v.z; bi = 4 * q + 2; }
        if (v.w > best) { best = v.w; bi = 4 * q + 3; }
    }
    float p = pp[off];
    float s = __fmul_rn(p, (float)bi);       // score = p * argmax_class (as float)
    s = (s > 0.25f) ? s : NEGF;              // SCORE_THR mask

    g_box[gid]   = box;
    g_area[gid]  = __fmul_rn(__fsub_rn(box.z, box.x), __fsub_rn(box.w, box.y));
    g_score[gid] = s;
}

// Ordered-float bijection (monotonic u32 keys)
__device__ __forceinline__ unsigned int ford(float f) {
    unsigned int u = __float_as_uint(f);
    return u ^ ((unsigned int)(((int)u) >> 31) | 0x80000000u);
}
__device__ __forceinline__ float fuord(unsigned int o) {
    unsigned int u = (o & 0x80000000u) ? (o ^ 0x80000000u) : ~o;
    return __uint_as_float(u);
}

// -------- cluster smem primitives --------
__device__ __forceinline__ unsigned int s2u(const void* p) {
    return (unsigned int)__cvta_generic_to_shared(p);
}
__device__ __forceinline__ unsigned int mapa_(unsigned int a, unsigned int r) {
    unsigned int d;
    asm("mapa.shared::cluster.u32 %0, %1, %2;" : "=r"(d) : "r"(a), "r"(r));
    return d;
}
__device__ __forceinline__ void stc64(unsigned int a, unsigned long long v) {
    asm volatile("st.shared::cluster.b64 [%0], %1;" :: "r"(a), "l"(v) : "memory");
}
__device__ __forceinline__ void arrive_rc(unsigned int a) {
    asm volatile("mbarrier.arrive.release.cluster.shared::cluster.b64 _, [%0];"
                 :: "r"(a) : "memory");
}
__device__ __forceinline__ void bar_init(unsigned int a, unsigned int n) {
    asm volatile("mbarrier.init.shared.b64 [%0], %1;" :: "r"(a), "r"(n) : "memory");
}
__device__ __forceinline__ void wait_par(unsigned int a, unsigned int ph) {
    unsigned int done;
    asm volatile(
        "{\n\t.reg .pred p;\n\t"
        "mbarrier.try_wait.parity.acquire.cluster.shared::cta.b64 p, [%1], %2;\n\t"
        "selp.b32 %0, 1, 0, p;\n\t}"
        : "=r"(done) : "r"(a), "r"(ph) : "memory");
    if (!done) {
        asm volatile(
            "{\n\t.reg .pred P;\n"
            "W%=:\n\t"
            "mbarrier.try_wait.parity.acquire.cluster.shared::cta.b64 P, [%0], %1, 0x989680;\n\t"
            "@P bra D%=;\n\t"
            "bra W%=;\n"
            "D%=:\n\t}"
            :: "r"(a), "r"(ph) : "memory");
    }
}
__device__ __forceinline__ unsigned long long packf2(float lo, float hi) {
    return ((unsigned long long)__float_as_uint(hi) << 32) | __float_as_uint(lo);
}

// ---------------------------------------------------------------------------
// Stage 2: sequential NMS. 8-CTA cluster per batch, register-resident anchors.
// Per iteration: warp REDUX argmax -> DSMEM push to rank0 hub (mbarrier,
// count=64) -> hub reduces 64 candidates -> DSMEM winner broadcast (mbarrier,
// count=1 per CTA). No __syncthreads / cluster.sync in the loop.
// ---------------------------------------------------------------------------
__global__ void __cluster_dims__(CSIZE, 1, 1) __launch_bounds__(TPB, 1)
nms_kernel(float* __restrict__ out, int out_size)
{
    cg::cluster_group cluster = cg::this_cluster();
    extern __shared__ unsigned char smem[];
    float4* sbox = reinterpret_cast<float4*>(smem + SBOX_OFF);
    unsigned long long* slots  = reinterpret_cast<unsigned long long*>(smem + SLOT_OFF); // [2][64][4]
    unsigned long long* winner = reinterpret_cast<unsigned long long*>(smem + WIN_OFF);  // [2][4]

    const unsigned int smem_base = s2u(smem);
    const unsigned int gbar = smem_base + BAR_OFF;        // gather[b] at +8*b
    const unsigned int bbar = smem_base + BAR_OFF + 16;   // bcast[b]  at +8*b

    const int t    = threadIdx.x;
    const int wid  = t >> 5;
    const int lane = t & 31;
    const int batch = blockIdx.x >> 3;
    const int rank  = blockIdx.x & 7;
    const int base  = rank * PER_CTA;
    const int gw    = rank * NWARP + wid;   // cluster-global warp id

    float y1[KMAX], x1[KMAX], y2[KMAX], x2[KMAX], ar[KMAX];
    unsigned int so[KMAX];

    #pragma unroll
    for (int k = 0; k < KMAX; k++) {
        int l = k * TPB + t;
        if (l < PER_CTA) {
            int g = batch * NANCH + base + l;
            float4 bx = g_box[g];
            y1[k] = bx.x; x1[k] = bx.y; y2[k] = bx.z; x2[k] = bx.w;
            ar[k] = g_area[g];
            so[k] = ford(g_score[g]);
            sbox[l] = bx;
        }
    }

    if (t == 0) {
        bar_init(gbar + 0, GWARPS);
        bar_init(gbar + 8, GWARPS);
        bar_init(bbar + 0, 1);
        bar_init(bbar + 8, 1);
    }

    // initial per-thread argmax (ascending k + strict '>' == smallest-index tie-break)
    unsigned int bord = 0; int bj = base + t;
    #pragma unroll
    for (int k = 0; k < KMAX; k++) {
        int l = k * TPB + t;
        if (l < PER_CTA) {
            if (so[k] > bord) { bord = so[k]; bj = base + l; }
        }
    }

    cluster.sync();   // barriers + sbox visible cluster-wide before first sends

    int cnt = 0;

    for (int it = 0; it < 100; ++it) {
        const int b = it & 1;
        const unsigned int ph = (it >> 1) & 1;

        // --- warp argmax via two-phase REDUX: max ord, then min idx among ties ---
        unsigned int mo = __reduce_max_sync(FULLM, bord);
        unsigned int cand = (bord == mo) ? (unsigned int)bj : 0xFFFFFFFFu;
        unsigned int mi = __reduce_min_sync(FULLM, cand);

        if (lane == 0) {
            float4 bx = sbox[mi - base];   // warp winner always in this CTA
            unsigned int sl = mapa_(smem_base + SLOT_OFF + (b * GWARPS + gw) * 32, 0);
            stc64(sl,      ((unsigned long long)mo << 32) | mi);
            stc64(sl + 8,  packf2(bx.x, bx.y));
            stc64(sl + 16, packf2(bx.z, bx.w));
            arrive_rc(mapa_(gbar + b * 8, 0));
        }

        // --- hub: rank0 warp0 reduces 64 candidates, broadcasts winner ---
        if (rank == 0 && wid == 0) {
            wait_par(gbar + b * 8, ph);
            unsigned long long k0 = slots[(b * GWARPS + lane) * 4];
            unsigned long long k1 = slots[(b * GWARPS + lane + 32) * 4];
            unsigned int o0 = (unsigned int)(k0 >> 32), i0 = (unsigned int)k0;
            unsigned int o1 = (unsigned int)(k1 >> 32), i1 = (unsigned int)k1;
            bool sel1 = (o1 > o0) || (o1 == o0 && i1 < i0);
            unsigned int o = sel1 ? o1 : o0;
            unsigned int i = sel1 ? i1 : i0;
            int which = sel1 ? (lane + 32) : lane;

            unsigned int mo2 = __reduce_max_sync(FULLM, o);
            unsigned int ci  = (o == mo2) ? i : 0xFFFFFFFFu;
            unsigned int mi2 = __reduce_min_sync(FULLM, ci);
            unsigned int bal = __ballot_sync(FULLM, (o == mo2) && (i == mi2));
            int wl = __ffs(bal) - 1;
            int wslot = __shfl_sync(FULLM, which, wl);
            unsigned long long wb1 = slots[(b * GWARPS + wslot) * 4 + 1];
            unsigned long long wb2 = slots[(b * GWARPS + wslot) * 4 + 2];

            if (lane < CSIZE) {
                unsigned int wa = mapa_(smem_base + WIN_OFF + b * 32, lane);
                stc64(wa,      ((unsigned long long)mo2 << 32) | mi2);
                stc64(wa + 8,  wb1);
                stc64(wa + 16, wb2);
                arrive_rc(mapa_(bbar + b * 8, lane));
            }
        }

        // --- all warps receive the winner ---
        wait_par(bbar + b * 8, ph);
        unsigned long long wk  = winner[b * 4];
        unsigned long long wb1 = winner[b * 4 + 1];
        unsigned long long wb2 = winner[b * 4 + 2];
        unsigned int mo_g = (unsigned int)(wk >> 32);
        int   wj  = (int)(unsigned int)wk;
        float ws  = fuord(mo_g);
        float wy1 = __uint_as_float((unsigned int)wb1);
        float wx1 = __uint_as_float((unsigned int)(wb1 >> 32));
        float wy2 = __uint_as_float((unsigned int)wb2);
        float wx2 = __uint_as_float((unsigned int)(wb2 >> 32));
        bool valid = ws > -5.0e8f;   // NEG * 0.5

        if (rank == 0 && t == 0) {
            int ob = (batch * 100 + it) * 6;
            if (valid && ob + 5 < out_size) {
                out[ob + 0] = fminf(fmaxf(wy1, 0.0f), 1.0f);
                out[ob + 1] = fminf(fmaxf(wx1, 0.0f), 1.0f);
                out[ob + 2] = fminf(fmaxf(wy2, 0.0f), 1.0f);
                out[ob + 3] = fminf(fmaxf(wx2, 0.0f), 1.0f);
                out[ob + 4] = ws;
                out[ob + 5] = 0.0f;
            }
            if (valid) cnt++;
        }
        if (!valid) break;   // uniform across cluster

        // --- suppress + fused next per-thread argmax (register-resident) ---
        float warea = __fmul_rn(__fsub_rn(wy2, wy1), __fsub_rn(wx2, wx1));
        int rsel = wj - (base + t);   // == k*TPB iff this thread owns the winner
        bord = 0; bj = base + t;
        bool need = false;

        #pragma unroll
        for (int k = 0; k < KMAX; k++) {
            int l = k * TPB + t;
            if (l < PER_CTA) {
                float ih = fmaxf(__fsub_rn(fminf(wy2, y2[k]), fmaxf(wy1, y1[k])), 0.0f);
                float iw = fmaxf(__fsub_rn(fminf(wx2, x2[k]), fmaxf(wx1, x1[k])), 0.0f);
                float inter = __fmul_rn(ih, iw);
                float uni   = __fsub_rn(__fadd_rn(warea, ar[k]), inter);
                float i2  = __fadd_rn(inter, inter);
                // thr = RN(uni*(1+2^-22)) — strictly above the 0.5+2^-25 div midpoint
                float thr = __fmaf_rn(uni, 2.384185791015625e-7f, uni);
                bool upos = uni > 0.0f;
                bool fast_t = upos && (i2 >= thr);
                need = need || (upos && (i2 > uni) && (i2 < thr));
                bool supp = fast_t || (rsel == k * TPB);
                so[k] = supp ? ORDNEG : so[k];
                if (so[k] > bord) { bord = so[k]; bj = base + l; }
            }
        }
        if (need) {
            // Exact-division fixup for the (astronomically rare) ambiguous band.
            #pragma unroll
            for (int k = 0; k < KMAX; k++) {
                int l = k * TPB + t;
                if (l < PER_CTA) {
                    float ih = fmaxf(__fsub_rn(fminf(wy2, y2[k]), fmaxf(wy1, y1[k])), 0.0f);
                    float iw = fmaxf(__fsub_rn(fminf(wx2, x2[k]), fmaxf(wx1, x1[k])), 0.0f);
                    float inter = __fmul_rn(ih, iw);
                    float uni   = __fsub_rn(__fadd_rn(warea, ar[k]), inter);
                    float i2  = __fadd_rn(inter, inter);
                    float thr = __fmaf_rn(uni, 2.384185791015625e-7f, uni);
                    if (uni > 0.0f && i2 > uni && i2 < thr) {
                        if (__fdiv_rn(inter, uni) > 0.5f) so[k] = ORDNEG;
                    }
                }
            }
            bord = 0; bj = base + t;
            #pragma unroll
            for (int k = 0; k < KMAX; k++) {
                int l = k * TPB + t;
                if (l < PER_CTA) {
                    if (so[k] > bord) { bord = so[k]; bj = base + l; }
                }
            }
        }
    }

    if (rank == 0 && t == 0) {
        int vi = BATCH * 100 * 6 + batch;
        if (vi < out_size) out[vi] = (float)cnt;
    }
    cluster.sync();   // no CTA may exit while peers may still target its DSMEM
}

// ---------------------------------------------------------------------------
extern "C" void kernel_launch(void* const* d_in, const int* in_sizes, int n_in,
                              void* d_out, int out_size)
{
    const float* b20 = (const float*)d_in[0];
    const float* p20 = (const float*)d_in[1];
    const float* c20 = (const float*)d_in[2];
    const float* b40 = (const float*)d_in[3];
    const float* p40 = (const float*)d_in[4];
    const float* c40 = (const float*)d_in[5];
    const float* b80 = (const float*)d_in[6];
    const float* p80 = (const float*)d_in[7];
    const float* c80 = (const float*)d_in[8];
    float* out = (float*)d_out;

    int total = BATCH * NANCH;
    int blocks = (total + TPB - 1) / TPB;
    prep_kernel<<<blocks, TPB>>>(b20, p20, c20, b40, p40, c40, b80, p80, c80, out, out_size);

    cudaFuncSetAttribute(nms_kernel, cudaFuncAttributeMaxDynamicSharedMemorySize, SMEM_TOT);
    nms_kernel<<<BATCH * CSIZE, TPB, SMEM_TOT>>>(out, out_size);
}

// round 7
// speedup vs baseline: 1.0376x; 1.0125x over previous
#include <cuda_runtime.h>
#include <cooperative_groups.h>

namespace cg = cooperative_groups;

#define NANCH 25200
#define BATCH 8
#define NEGF  (-1e9f)
#define TPB   256
#define NWARP 8

// ord(NEGF) = ~bits(-1e9f)
#define ORDNEG 0x319194D7u
// ord(-5e8f) : validity threshold (score > NEG*0.5)
#define ORDVAL 0x321194D7u
#define FULLM  0xFFFFFFFFu

// Scratch (static __device__ — no allocation allowed)
__device__ float4 g_box[BATCH * NANCH];
__device__ float  g_area[BATCH * NANCH];
__device__ float  g_score[BATCH * NANCH];

// ---------------------------------------------------------------------------
// Stage 1: class argmax, score mask, box/area gather. Also zero-fills d_out.
// ---------------------------------------------------------------------------
__global__ void prep_kernel(const float* __restrict__ b20, const float* __restrict__ p20, const float* __restrict__ c20,
                            const float* __restrict__ b40, const float* __restrict__ p40, const float* __restrict__ c40,
                            const float* __restrict__ b80, const float* __restrict__ p80, const float* __restrict__ c80,
                            float* __restrict__ out, int out_size)
{
    int gid = blockIdx.x * blockDim.x + threadIdx.x;
    if (gid < out_size) out[gid] = 0.0f;
    if (gid >= BATCH * NANCH) return;

    int b = gid / NANCH;
    int j = gid - b * NANCH;

    const float *bb, *pp, *cc;
    int off;
    if (j < 1200)      { bb = b20; pp = p20; cc = c20; off = b * 1200  + j; }
    else if (j < 6000) { bb = b40; pp = p40; cc = c40; off = b * 4800  + (j - 1200); }
    else               { bb = b80; pp = p80; cc = c80; off = b * 19200 + (j - 6000); }

    float4 box = reinterpret_cast<const float4*>(bb)[off];
    const float4* crow = reinterpret_cast<const float4*>(cc) + off * 20;

    float best = __int_as_float(0xff800000); // -inf
    int bi = 0;
    #pragma unroll
    for (int q = 0; q < 20; q++) {
        float4 v = crow[q];
        if (v.x > best) { best = v.x; bi = 4 * q + 0; }
        if (v.y > best) { best = v.y; bi = 4 * q + 1; }
        if (v.z > best) { best = v.z; bi = 4 * q + 2; }
        if (v.w > best) { best = v.w; bi = 4 * q + 3; }
    }
    float p = pp[off];
    float s = __fmul_rn(p, (float)bi);       // score = p * argmax_class (as float)
    s = (s > 0.25f) ? s : NEGF;              // SCORE_THR mask

    g_box[gid]   = box;
    g_area[gid]  = __fmul_rn(__fsub_rn(box.z, box.x), __fsub_rn(box.w, box.y));
    g_score[gid] = s;
}

// Ordered-float bijection (monotonic u32 keys)
__device__ __forceinline__ unsigned int ford(float f) {
    unsigned int u = __float_as_uint(f);
    return u ^ ((unsigned int)(((int)u) >> 31) | 0x80000000u);
}
__device__ __forceinline__ float fuord(unsigned int o) {
    unsigned int u = (o & 0x80000000u) ? (o ^ 0x80000000u) : ~o;
    return __uint_as_float(u);
}

// -------- cluster smem primitives --------
__device__ __forceinline__ unsigned int s2u(const void* p) {
    return (unsigned int)__cvta_generic_to_shared(p);
}
__device__ __forceinline__ unsigned int mapa_(unsigned int a, unsigned int r) {
    unsigned int d;
    asm("mapa.shared::cluster.u32 %0, %1, %2;" : "=r"(d) : "r"(a), "r"(r));
    return d;
}
__device__ __forceinline__ void stc64(unsigned int a, unsigned long long v) {
    asm volatile("st.shared::cluster.b64 [%0], %1;" :: "r"(a), "l"(v) : "memory");
}
__device__ __forceinline__ void arrive_rc(unsigned int a) {
    asm volatile("mbarrier.arrive.release.cluster.shared::cluster.b64 _, [%0];"
                 :: "r"(a) : "memory");
}
__device__ __forceinline__ void bar_init(unsigned int a, unsigned int n) {
    asm volatile("mbarrier.init.shared.b64 [%0], %1;" :: "r"(a), "r"(n) : "memory");
}
__device__ __forceinline__ void wait_par(unsigned int a, unsigned int ph) {
    unsigned int done;
    asm volatile(
        "{\n\t.reg .pred p;\n\t"
        "mbarrier.try_wait.parity.acquire.cluster.shared::cta.b64 p, [%1], %2;\n\t"
        "selp.b32 %0, 1, 0, p;\n\t}"
        : "=r"(done) : "r"(a), "r"(ph) : "memory");
    if (!done) {
        asm volatile(
            "{\n\t.reg .pred P;\n"
            "W%=:\n\t"
            "mbarrier.try_wait.parity.acquire.cluster.shared::cta.b64 P, [%0], %1, 0x989680;\n\t"
            "@P bra D%=;\n\t"
            "bra W%=;\n"
            "D%=:\n\t}"
            :: "r"(a), "r"(ph) : "memory");
    }
}
__device__ __forceinline__ unsigned long long packf2(float lo, float hi) {
    return ((unsigned long long)__float_as_uint(hi) << 32) | __float_as_uint(lo);
}

// ---------------------------------------------------------------------------
// Stage 2: sequential NMS, templated on cluster size CS.
// Per iteration: warp REDUX argmax -> CTA reduce (smem+syncthreads) ->
// warp0 lanes store CTA winner into ALL CS peers' candidate slots + arrive
// (flat all-to-all, ONE DSMEM hop) -> each warp reduces CS candidates
// locally -> suppress (register-resident anchors).
// ---------------------------------------------------------------------------
template<int CS>
__global__ void __launch_bounds__(TPB, 1)
nms_kernel(float* __restrict__ out, int out_size)
{
    constexpr int PER  = NANCH / CS;
    constexpr int KM   = (PER + TPB - 1) / TPB;
    constexpr int SBOX_BYTES = PER * 16;
    constexpr int WSLOT_OFF  = SBOX_BYTES;              // [NWARP][4 u64]
    constexpr int CAND_OFF   = WSLOT_OFF + NWARP * 32;  // [2][CS][4 u64]
    constexpr int XBAR_OFF   = CAND_OFF + 2 * CS * 32;  // xbar[2]

    cg::cluster_group cluster = cg::this_cluster();
    extern __shared__ unsigned char smem[];
    float4* sbox = reinterpret_cast<float4*>(smem);
    unsigned long long* wslot = reinterpret_cast<unsigned long long*>(smem + WSLOT_OFF);
    unsigned long long* candp = reinterpret_cast<unsigned long long*>(smem + CAND_OFF);

    const unsigned int smem_base = s2u(smem);
    const unsigned int xbar = smem_base + XBAR_OFF;

    const int t    = threadIdx.x;
    const int wid  = t >> 5;
    const int lane = t & 31;
    const int batch = blockIdx.x / CS;
    const int rank  = blockIdx.x % CS;
    const int base  = rank * PER;

    float y1[KM], x1[KM], y2[KM], x2[KM], ar[KM];
    unsigned int so[KM];

    #pragma unroll
    for (int k = 0; k < KM; k++) {
        int l = k * TPB + t;
        if (l < PER) {
            int g = batch * NANCH + base + l;
            float4 bx = g_box[g];
            y1[k] = bx.x; x1[k] = bx.y; y2[k] = bx.z; x2[k] = bx.w;
            ar[k] = g_area[g];
            so[k] = ford(g_score[g]);
            sbox[l] = bx;
        }
    }

    if (t == 0) {
        bar_init(xbar + 0, CS);
        bar_init(xbar + 8, CS);
    }

    // initial per-thread argmax (ascending k + strict '>' == smallest-index tie-break)
    unsigned int bord = 0; int bj = base + t;
    #pragma unroll
    for (int k = 0; k < KM; k++) {
        int l = k * TPB + t;
        if (l < PER) {
            if (so[k] > bord) { bord = so[k]; bj = base + l; }
        }
    }

    cluster.sync();   // barriers + sbox visible cluster-wide before first sends

    int cnt = 0;

    for (int it = 0; it < 100; ++it) {
        const int b = it & 1;
        const unsigned int ph = (it >> 1) & 1;

        // --- warp argmax: two-phase REDUX (max ord, then min idx among ties) ---
        unsigned int mo = __reduce_max_sync(FULLM, bord);
        unsigned int cd = (bord == mo) ? (unsigned int)bj : 0xFFFFFFFFu;
        unsigned int mi = __reduce_min_sync(FULLM, cd);

        if (lane == 0) {
            float4 bx = sbox[mi - base];   // warp winner always in this CTA
            unsigned long long* w = wslot + wid * 4;
            w[0] = ((unsigned long long)mo << 32) | mi;
            w[1] = packf2(bx.x, bx.y);
            w[2] = packf2(bx.z, bx.w);
        }
        __syncthreads();

        // --- warp0: reduce NWARP winners, send CTA winner to all CS peers ---
        if (wid == 0) {
            unsigned long long wb1 = 0, wb2 = 0;
            unsigned int o = 0, i = 0xFFFFFFFFu;
            if (lane < NWARP) {
                const unsigned long long* w = wslot + lane * 4;
                unsigned long long kk = w[0];
                wb1 = w[1]; wb2 = w[2];
                o = (unsigned int)(kk >> 32); i = (unsigned int)kk;
            }
            unsigned int mo2 = __reduce_max_sync(FULLM, o);
            unsigned int ci  = (o == mo2) ? i : 0xFFFFFFFFu;
            unsigned int mi2 = __reduce_min_sync(FULLM, ci);
            unsigned int bal = __ballot_sync(FULLM, (o == mo2) && (i == mi2));
            int wl = __ffs(bal) - 1;
            unsigned long long sb1 = __shfl_sync(FULLM, wb1, wl);
            unsigned long long sb2 = __shfl_sync(FULLM, wb2, wl);

            if (lane < CS) {
                unsigned int dst = mapa_(smem_base + CAND_OFF + (b * CS + rank) * 32, lane);
                stc64(dst,      ((unsigned long long)mo2 << 32) | mi2);
                stc64(dst + 8,  sb1);
                stc64(dst + 16, sb2);
                arrive_rc(mapa_(xbar + b * 8, lane));
            }
        }

        // --- all warps: wait for CS arrivals, reduce CS candidates locally ---
        wait_par(xbar + b * 8, ph);
        unsigned long long cb1 = 0, cb2 = 0;
        unsigned int o = 0, i = 0xFFFFFFFFu;
        if (lane < CS) {
            const unsigned long long* c = candp + (b * CS + lane) * 4;
            unsigned long long kk = c[0];
            cb1 = c[1]; cb2 = c[2];
            o = (unsigned int)(kk >> 32); i = (unsigned int)kk;
        }
        unsigned int mo_g = __reduce_max_sync(FULLM, o);
        unsigned int ci   = (o == mo_g) ? i : 0xFFFFFFFFu;
        unsigned int mi_g = __reduce_min_sync(FULLM, ci);
        unsigned int bal  = __ballot_sync(FULLM, (o == mo_g) && (i == mi_g));
        int wl = __ffs(bal) - 1;
        unsigned long long wb1 = __shfl_sync(FULLM, cb1, wl);
        unsigned long long wb2 = __shfl_sync(FULLM, cb2, wl);

        int   wj  = (int)mi_g;
        float wy1 = __uint_as_float((unsigned int)wb1);
        float wx1 = __uint_as_float((unsigned int)(wb1 >> 32));
        float wy2 = __uint_as_float((unsigned int)wb2);
        float wx2 = __uint_as_float((unsigned int)(wb2 >> 32));
        bool valid = mo_g > ORDVAL;   // score > NEG*0.5 (ord-monotonic)

        if (rank == 0 && t == 0) {
            int ob = (batch * 100 + it) * 6;
            if (valid && ob + 5 < out_size) {
                out[ob + 0] = fminf(fmaxf(wy1, 0.0f), 1.0f);
                out[ob + 1] = fminf(fmaxf(wx1, 0.0f), 1.0f);
                out[ob + 2] = fminf(fmaxf(wy2, 0.0f), 1.0f);
                out[ob + 3] = fminf(fmaxf(wx2, 0.0f), 1.0f);
                out[ob + 4] = fuord(mo_g);
                out[ob + 5] = 0.0f;
            }
            if (valid) cnt++;
        }
        if (!valid) break;   // uniform across cluster (same reduce everywhere)

        // --- suppress + fused next per-thread argmax (register-resident) ---
        float warea = __fmul_rn(__fsub_rn(wy2, wy1), __fsub_rn(wx2, wx1));
        int rsel = wj - (base + t);   // == k*TPB iff this thread owns the winner
        bord = 0; bj = base + t;
        bool need = false;

        #pragma unroll
        for (int k = 0; k < KM; k++) {
            int l = k * TPB + t;
            if (l < PER) {
                float ih = fmaxf(__fsub_rn(fminf(wy2, y2[k]), fmaxf(wy1, y1[k])), 0.0f);
                float iw = fmaxf(__fsub_rn(fminf(wx2, x2[k]), fmaxf(wx1, x1[k])), 0.0f);
                float inter = __fmul_rn(ih, iw);
                float uni   = __fsub_rn(__fadd_rn(warea, ar[k]), inter);
                float i2  = __fadd_rn(inter, inter);
                // thr = RN(uni*(1+2^-22)) — strictly above the 0.5+2^-25 div midpoint
                float thr = __fmaf_rn(uni, 2.384185791015625e-7f, uni);
                bool upos = uni > 0.0f;
                bool fast_t = upos && (i2 >= thr);
                need = need || (upos && (i2 > uni) && (i2 < thr));
                bool supp = fast_t || (rsel == k * TPB);
                so[k] = supp ? ORDNEG : so[k];
                if (so[k] > bord) { bord = so[k]; bj = base + l; }
            }
        }
        if (need) {
            // Exact-division fixup for the (astronomically rare) ambiguous band.
            #pragma unroll
            for (int k = 0; k < KM; k++) {
                int l = k * TPB + t;
                if (l < PER) {
                    float ih = fmaxf(__fsub_rn(fminf(wy2, y2[k]), fmaxf(wy1, y1[k])), 0.0f);
                    float iw = fmaxf(__fsub_rn(fminf(wx2, x2[k]), fmaxf(wx1, x1[k])), 0.0f);
                    float inter = __fmul_rn(ih, iw);
                    float uni   = __fsub_rn(__fadd_rn(warea, ar[k]), inter);
                    float i2  = __fadd_rn(inter, inter);
                    float thr = __fmaf_rn(uni, 2.384185791015625e-7f, uni);
                    if (uni > 0.0f && i2 > uni && i2 < thr) {
                        if (__fdiv_rn(inter, uni) > 0.5f) so[k] = ORDNEG;
                    }
                }
            }
            bord = 0; bj = base + t;
            #pragma unroll
            for (int k = 0; k < KM; k++) {
                int l = k * TPB + t;
                if (l < PER) {
                    if (so[k] > bord) { bord = so[k]; bj = base + l; }
                }
            }
        }
    }

    if (rank == 0 && t == 0) {
        int vi = BATCH * 100 * 6 + batch;
        if (vi < out_size) out[vi] = (float)cnt;
    }
    cluster.sync();   // no CTA may exit while peers may still target its DSMEM
}

// smem totals per cluster size
template<int CS> struct SmemTot {
    static constexpr int PER = NANCH / CS;
    static constexpr int v = PER * 16 + NWARP * 32 + 2 * CS * 32 + 16;
};

// ---------------------------------------------------------------------------
extern "C" void kernel_launch(void* const* d_in, const int* in_sizes, int n_in,
                              void* d_out, int out_size)
{
    const float* b20 = (const float*)d_in[0];
    const float* p20 = (const float*)d_in[1];
    const float* c20 = (const float*)d_in[2];
    const float* b40 = (const float*)d_in[3];
    const float* p40 = (const float*)d_in[4];
    const float* c40 = (const float*)d_in[5];
    const float* b80 = (const float*)d_in[6];
    const float* p80 = (const float*)d_in[7];
    const float* c80 = (const float*)d_in[8];
    float* out = (float*)d_out;

    int total = BATCH * NANCH;
    int blocks = (total + TPB - 1) / TPB;
    prep_kernel<<<blocks, TPB>>>(b20, p20, c20, b40, p40, c40, b80, p80, c80, out, out_size);

    // Prefer cluster=16 (non-portable); fall back to 8 if not grantable.
    cudaFuncSetAttribute(nms_kernel<16>, cudaFuncAttributeNonPortableClusterSizeAllowed, 1);
    cudaFuncSetAttribute(nms_kernel<16>, cudaFuncAttributeMaxDynamicSharedMemorySize, SmemTot<16>::v);
    cudaFuncSetAttribute(nms_kernel<8>,  cudaFuncAttributeMaxDynamicSharedMemorySize, SmemTot<8>::v);

    cudaLaunchConfig_t q = {};
    q.gridDim  = dim3(BATCH * 16, 1, 1);
    q.blockDim = dim3(TPB, 1, 1);
    q.dynamicSmemBytes = SmemTot<16>::v;
    q.stream = 0;
    int maxc = 0;
    cudaOccupancyMaxPotentialClusterSize(&maxc, nms_kernel<16>, &q);

    cudaLaunchAttribute at[1];
    at[0].id = cudaLaunchAttributeClusterDimension;

    if (maxc >= 16) {
        cudaLaunchConfig_t cfg = {};
        cfg.gridDim  = dim3(BATCH * 16, 1, 1);
        cfg.blockDim = dim3(TPB, 1, 1);
        cfg.dynamicSmemBytes = SmemTot<16>::v;
        cfg.stream = 0;
        at[0].val.clusterDim = {16, 1, 1};
        cfg.attrs = at; cfg.numAttrs = 1;
        cudaLaunchKernelEx(&cfg, nms_kernel<16>, out, out_size);
    } else {
        cudaLaunchConfig_t cfg = {};
        cfg.gridDim  = dim3(BATCH * 8, 1, 1);
        cfg.blockDim = dim3(TPB, 1, 1);
        cfg.dynamicSmemBytes = SmemTot<8>::v;
        cfg.stream = 0;
        at[0].val.clusterDim = {8, 1, 1};
        cfg.attrs = at; cfg.numAttrs = 1;
        cudaLaunchKernelEx(&cfg, nms_kernel<8>, out, out_size);
    }
}

// round 8
// speedup vs baseline: 1.3343x; 1.2860x over previous
#include <cuda_runtime.h>
#include <cooperative_groups.h>

namespace cg = cooperative_groups;

#define NANCH 25200
#define BATCH 8
#define NEGF  (-1e9f)
#define TPB   256
#define NWARP 8

// ord(NEGF) = ~bits(-1e9f)
#define ORDNEG 0x319194D7u
// ord(-5e8f) : validity threshold (score > NEG*0.5)
#define ORDVAL 0x321194D7u
#define FULLM  0xFFFFFFFFu

typedef unsigned int u32;
typedef unsigned long long u64;

// Scratch (static __device__ — no allocation allowed)
__device__ float4 g_box[BATCH * NANCH];
__device__ float  g_area[BATCH * NANCH];
__device__ float  g_score[BATCH * NANCH];

// ---------------------------------------------------------------------------
// Stage 1: class argmax, score mask, box/area gather. Also zero-fills d_out.
// ---------------------------------------------------------------------------
__global__ void prep_kernel(const float* __restrict__ b20, const float* __restrict__ p20, const float* __restrict__ c20,
                            const float* __restrict__ b40, const float* __restrict__ p40, const float* __restrict__ c40,
                            const float* __restrict__ b80, const float* __restrict__ p80, const float* __restrict__ c80,
                            float* __restrict__ out, int out_size)
{
    int gid = blockIdx.x * blockDim.x + threadIdx.x;
    if (gid < out_size) out[gid] = 0.0f;
    if (gid >= BATCH * NANCH) return;

    int b = gid / NANCH;
    int j = gid - b * NANCH;

    const float *bb, *pp, *cc;
    int off;
    if (j < 1200)      { bb = b20; pp = p20; cc = c20; off = b * 1200  + j; }
    else if (j < 6000) { bb = b40; pp = p40; cc = c40; off = b * 4800  + (j - 1200); }
    else               { bb = b80; pp = p80; cc = c80; off = b * 19200 + (j - 6000); }

    float4 box = reinterpret_cast<const float4*>(bb)[off];
    const float4* crow = reinterpret_cast<const float4*>(cc) + off * 20;

    float best = __int_as_float(0xff800000); // -inf
    int bi = 0;
    #pragma unroll
    for (int q = 0; q < 20; q++) {
        float4 v = crow[q];
        if (v.x > best) { best = v.x; bi = 4 * q + 0; }
        if (v.y > best) { best = v.y; bi = 4 * q + 1; }
        if (v.z > best) { best = v.z; bi = 4 * q + 2; }
        if (v.w > best) { best = v.w; bi = 4 * q + 3; }
    }
    float p = pp[off];
    float s = __fmul_rn(p, (float)bi);       // score = p * argmax_class (as float)
    s = (s > 0.25f) ? s : NEGF;              // SCORE_THR mask

    g_box[gid]   = box;
    g_area[gid]  = __fmul_rn(__fsub_rn(box.z, box.x), __fsub_rn(box.w, box.y));
    g_score[gid] = s;
}

// Ordered-float bijection (monotonic u32 keys)
__device__ __forceinline__ u32 ford(float f) {
    u32 u = __float_as_uint(f);
    return u ^ ((u32)(((int)u) >> 31) | 0x80000000u);
}
__device__ __forceinline__ float fuord(u32 o) {
    u32 u = (o & 0x80000000u) ? (o ^ 0x80000000u) : ~o;
    return __uint_as_float(u);
}

// -------- cluster smem primitives --------
__device__ __forceinline__ u32 s2u(const void* p) {
    return (u32)__cvta_generic_to_shared(p);
}
__device__ __forceinline__ u32 mapa_(u32 a, u32 r) {
    u32 d;
    asm("mapa.shared::cluster.u32 %0, %1, %2;" : "=r"(d) : "r"(a), "r"(r));
    return d;
}
__device__ __forceinline__ void stc64(u32 a, u64 v) {
    asm volatile("st.shared::cluster.b64 [%0], %1;" :: "r"(a), "l"(v) : "memory");
}
__device__ __forceinline__ void arrive_rc(u32 a) {
    asm volatile("mbarrier.arrive.release.cluster.shared::cluster.b64 _, [%0];"
                 :: "r"(a) : "memory");
}
__device__ __forceinline__ void bar_init(u32 a, u32 n) {
    asm volatile("mbarrier.init.shared.b64 [%0], %1;" :: "r"(a), "r"(n) : "memory");
}
__device__ __forceinline__ void wait_par(u32 a, u32 ph) {
    u32 done;
    asm volatile(
        "{\n\t.reg .pred p;\n\t"
        "mbarrier.try_wait.parity.acquire.cluster.shared::cta.b64 p, [%1], %2;\n\t"
        "selp.b32 %0, 1, 0, p;\n\t}"
        : "=r"(done) : "r"(a), "r"(ph) : "memory");
    if (!done) {
        asm volatile(
            "{\n\t.reg .pred P;\n"
            "W%=:\n\t"
            "mbarrier.try_wait.parity.acquire.cluster.shared::cta.b64 P, [%0], %1, 0x989680;\n\t"
            "@P bra D%=;\n\t"
            "bra W%=;\n"
            "D%=:\n\t}"
            :: "r"(a), "r"(ph) : "memory");
    }
}
__device__ __forceinline__ u64 packf2(float lo, float hi) {
    return ((u64)__float_as_uint(hi) << 32) | __float_as_uint(lo);
}

// key compare: (o,j) > (o',j')  — higher score wins, then smaller index
__device__ __forceinline__ bool kgt(u32 ao, u32 aj, u32 bo, u32 bj) {
    return (ao > bo) || (ao == bo && aj < bj);
}

// merge two descending-sorted top-2 pairs into one (standard top-2 merge)
__device__ __forceinline__ void top2_merge(u32& o1, u32& j1, u32& o2, u32& j2,
                                           u32 o1x, u32 j1x, u32 o2x, u32 j2x) {
    bool a = kgt(o1x, j1x, o1, j1);          // k1x > k1 ?
    u32 no1 = a ? o1x : o1, nj1 = a ? j1x : j1;
    u32 ro  = a ? o1  : o1x, rj = a ? j1  : j1x;   // runner-up of the two tops
    bool b2 = kgt(o2x, j2x, o2, j2);
    u32 co = b2 ? o2x : o2, cj = b2 ? j2x : j2;    // best of the two seconds
    bool c2 = kgt(ro, rj, co, cj);
    o2 = c2 ? ro : co;  j2 = c2 ? rj : cj;
    o1 = no1;           j1 = nj1;
}

// ---------------------------------------------------------------------------
// Stage 2: batched NMS. Per exchange ROUND each CTA ships its top-2 (keys +
// boxes) to all CS peers (one DSMEM hop). Then every warp redundantly runs the
// selection over the 2*CS shipped candidates, emitting multiple winners per
// round with zero cross-CTA traffic, suppressing both the candidate list
// (exact division IoU) and its register-resident scores per winner.
// Soundness: a CTA's unlisted boxes all have key < its entry-2's ORIGINAL key,
// so selection continues while every exhausted CTA's bound is dominated.
// ---------------------------------------------------------------------------
template<int CS>
__global__ void __launch_bounds__(TPB, 1)
nms_kernel(float* __restrict__ out, int out_size)
{
    constexpr int PER  = NANCH / CS;
    constexpr int KM   = (PER + TPB - 1) / TPB;
    constexpr int WS_OFF   = PER * 16;              // u32 ws[32] (8 warps x top2)
    constexpr int CAND_OFF = WS_OFF + 128;          // [2][CS][2 slots][32B]
    constexpr int XBAR_OFF = CAND_OFF + 128 * CS;   // xbar[2]

    cg::cluster_group cluster = cg::this_cluster();
    extern __shared__ unsigned char smem[];
    float4* sbox = reinterpret_cast<float4*>(smem);
    u32*    ws   = reinterpret_cast<u32*>(smem + WS_OFF);
    u64*    cand = reinterpret_cast<u64*>(smem + CAND_OFF);

    const u32 smem_base = s2u(smem);
    const u32 xbar = smem_base + XBAR_OFF;

    const int t    = threadIdx.x;
    const int wid  = t >> 5;
    const int lane = t & 31;
    const int batch = blockIdx.x / CS;
    const int rank  = blockIdx.x % CS;
    const int base  = rank * PER;

    float y1[KM], x1[KM], y2[KM], x2[KM], ar[KM];
    u32 so[KM];

    #pragma unroll
    for (int k = 0; k < KM; k++) {
        int l = k * TPB + t;
        if (l < PER) {
            int g = batch * NANCH + base + l;
            float4 bx = g_box[g];
            y1[k] = bx.x; x1[k] = bx.y; y2[k] = bx.z; x2[k] = bx.w;
            ar[k] = g_area[g];
            so[k] = ford(g_score[g]);
            sbox[l] = bx;
        }
    }

    if (t == 0) {
        bar_init(xbar + 0, CS);
        bar_init(xbar + 8, CS);
    }

    cluster.sync();   // barriers + sbox visible cluster-wide before first sends

    int emitted = 0;
    bool done = false;

    for (int rnd = 0; !done && emitted < 100; ++rnd) {
        const int b = rnd & 1;
        const u32 ph = (rnd >> 1) & 1;

        // ---- per-thread top-2 over registers (first-index tie-break) ----
        u32 o1 = 0, j1 = 0xFFFFFFFFu, o2 = 0, j2 = 0xFFFFFFFFu;
        #pragma unroll
        for (int k = 0; k < KM; k++) {
            int l = k * TPB + t;
            if (l < PER) {
                u32 s = so[k], idx = (u32)(base + l);
                if (s > o1)      { o2 = o1; j2 = j1; o1 = s; j1 = idx; }
                else if (s > o2) { o2 = s;  j2 = idx; }
            }
        }
        // ---- warp top-2 merge (5-step xor shuffle) ----
        #pragma unroll
        for (int off = 16; off > 0; off >>= 1) {
            u32 o1x = __shfl_xor_sync(FULLM, o1, off);
            u32 j1x = __shfl_xor_sync(FULLM, j1, off);
            u32 o2x = __shfl_xor_sync(FULLM, o2, off);
            u32 j2x = __shfl_xor_sync(FULLM, j2, off);
            top2_merge(o1, j1, o2, j2, o1x, j1x, o2x, j2x);
        }
        if (lane == 0) {
            ws[wid * 4 + 0] = o1; ws[wid * 4 + 1] = j1;
            ws[wid * 4 + 2] = o2; ws[wid * 4 + 3] = j2;
        }
        __syncthreads();

        // ---- warp0: CTA top-2 over 16 warp entries, send to all peers ----
        if (wid == 0) {
            u32 O1 = 0, J1 = 0xFFFFFFFFu, O2 = 0, J2 = 0xFFFFFFFFu;
            if (lane < 16) {
                int w = lane >> 1, s = lane & 1;
                O1 = ws[w * 4 + s * 2];
                J1 = ws[w * 4 + s * 2 + 1];
            }
            #pragma unroll
            for (int off = 16; off > 0; off >>= 1) {
                u32 o1x = __shfl_xor_sync(FULLM, O1, off);
                u32 j1x = __shfl_xor_sync(FULLM, J1, off);
                u32 o2x = __shfl_xor_sync(FULLM, O2, off);
                u32 j2x = __shfl_xor_sync(FULLM, J2, off);
                top2_merge(O1, J1, O2, J2, o1x, j1x, o2x, j2x);
            }
            // all lanes now agree on (O1,J1,O2,J2); boxes are in this CTA's sbox
            if (lane < CS) {
                float4 bA = sbox[J1 - base];
                float4 bB = sbox[J2 - base];
                u32 dst = mapa_(smem_base + CAND_OFF + (u32)((b * CS + rank) * 64), (u32)lane);
                stc64(dst + 0,  ((u64)J1 << 32) | O1);
                stc64(dst + 8,  packf2(bA.x, bA.y));
                stc64(dst + 16, packf2(bA.z, bA.w));
                stc64(dst + 32, ((u64)J2 << 32) | O2);
                stc64(dst + 40, packf2(bB.x, bB.y));
                stc64(dst + 48, packf2(bB.z, bB.w));
                arrive_rc(mapa_(xbar + b * 8, (u32)lane));
            }
        }

        // ---- receive 2*CS candidates (lane -> one entry) ----
        wait_par(xbar + b * 8, ph);
        u32 eo = 0, ej = 0xFFFFFFFFu;
        float ey1 = 0, ex1 = 0, ey2 = 0, ex2 = 0;
        u32 bo = 0, bjv = 0xFFFFFFFFu;   // slot-1 ORIGINAL key (hidden-box bound)
        bool alive = false;
        if (lane < 2 * CS) {
            int c = lane & (CS - 1);
            int s = lane / CS;
            const u64* e = cand + (size_t)((b * CS + c) * 2 + s) * 4;
            u64 kw = e[0], p1 = e[1], p2 = e[2];
            eo = (u32)kw; ej = (u32)(kw >> 32);
            ey1 = __uint_as_float((u32)p1);  ex1 = __uint_as_float((u32)(p1 >> 32));
            ey2 = __uint_as_float((u32)p2);  ex2 = __uint_as_float((u32)(p2 >> 32));
            alive = true;
            if (s == 1) { bo = eo; bjv = ej; }
        }

        // ---- central multi-select loop (every warp redundantly) ----
        while (emitted < 100) {
            u32 am = __ballot_sync(FULLM, alive);
            if (am == 0) break;                               // round exhausted

            u32 mo = __reduce_max_sync(FULLM, alive ? eo : 0u);
            if (mo <= ORDVAL) { done = true; break; }          // no valid boxes left
            u32 mi = __reduce_min_sync(FULLM, (alive && eo == mo) ? ej : 0xFFFFFFFFu);

            // soundness vs exhausted CTAs' hidden boxes
            bool exh = false;
            if (lane >= CS && lane < 2 * CS) {
                int c = lane - CS;
                exh = !((am >> c) & 1u) && !((am >> lane) & 1u);
            }
            u32 bh = __reduce_max_sync(FULLM, exh ? bo : 0u);
            if (bh > mo) break;                                // hidden box may win
            if (bh != 0 && bh == mo) {
                u32 bj = __reduce_min_sync(FULLM, (exh && bo == bh) ? bjv : 0xFFFFFFFFu);
                if (mi > bj) break;                            // hidden tie may win
            }

            // broadcast winner box
            u32 sel = __ballot_sync(FULLM, alive && eo == mo && ej == mi);
            int sl = __ffs(sel) - 1;
            float wy1 = __shfl_sync(FULLM, ey1, sl);
            float wx1 = __shfl_sync(FULLM, ex1, sl);
            float wy2 = __shfl_sync(FULLM, ey2, sl);
            float wx2 = __shfl_sync(FULLM, ex2, sl);

            if (rank == 0 && t == 0) {
                int ob = (batch * 100 + emitted) * 6;
                if (ob + 5 < out_size) {
                    out[ob + 0] = fminf(fmaxf(wy1, 0.0f), 1.0f);
                    out[ob + 1] = fminf(fmaxf(wx1, 0.0f), 1.0f);
                    out[ob + 2] = fminf(fmaxf(wy2, 0.0f), 1.0f);
                    out[ob + 3] = fminf(fmaxf(wx2, 0.0f), 1.0f);
                    out[ob + 4] = fuord(mo);
                    out[ob + 5] = 0.0f;
                }
            }
            emitted++;

            // kill selected + suppress candidate list (exact division IoU)
            if (ej == mi) alive = false;
            if (alive) {
                float ih = fmaxf(__fsub_rn(fminf(wy2, ey2), fmaxf(wy1, ey1)), 0.0f);
                float iw = fmaxf(__fsub_rn(fminf(wx2, ex2), fmaxf(wx1, ex1)), 0.0f);
                float inter = __fmul_rn(ih, iw);
                float earea = __fmul_rn(__fsub_rn(ey2, ey1), __fsub_rn(ex2, ex1));
                float wareaC = __fmul_rn(__fsub_rn(wy2, wy1), __fsub_rn(wx2, wx1));
                float uni = __fsub_rn(__fadd_rn(wareaC, earea), inter);
                if (uni > 0.0f && __fdiv_rn(inter, uni) > 0.5f) alive = false;
            }

            // suppress register-resident scores (all warps, own anchors)
            {
                float warea = __fmul_rn(__fsub_rn(wy2, wy1), __fsub_rn(wx2, wx1));
                int rsel = (int)mi - (base + t);   // == k*TPB iff this thread owns winner
                bool need = false;
                #pragma unroll
                for (int k = 0; k < KM; k++) {
                    int l = k * TPB + t;
                    if (l < PER) {
                        float ih = fmaxf(__fsub_rn(fminf(wy2, y2[k]), fmaxf(wy1, y1[k])), 0.0f);
                        float iw = fmaxf(__fsub_rn(fminf(wx2, x2[k]), fmaxf(wx1, x1[k])), 0.0f);
                        float inter = __fmul_rn(ih, iw);
                        float uni   = __fsub_rn(__fadd_rn(warea, ar[k]), inter);
                        float i2  = __fadd_rn(inter, inter);
                        // thr = RN(uni*(1+2^-22)) — strictly above the 0.5+2^-25 midpoint
                        float thr = __fmaf_rn(uni, 2.384185791015625e-7f, uni);
                        bool upos = uni > 0.0f;
                        bool fast_t = upos && (i2 >= thr);
                        need = need || (upos && (i2 > uni) && (i2 < thr));
                        bool supp = fast_t || (rsel == k * TPB);
                        so[k] = supp ? ORDNEG : so[k];
                    }
                }
                if (need) {
                    // exact-division fixup (astronomically rare band)
                    #pragma unroll
                    for (int k = 0; k < KM; k++) {
                        int l = k * TPB + t;
                        if (l < PER) {
                            float ih = fmaxf(__fsub_rn(fminf(wy2, y2[k]), fmaxf(wy1, y1[k])), 0.0f);
                            float iw = fmaxf(__fsub_rn(fminf(wx2, x2[k]), fmaxf(wx1, x1[k])), 0.0f);
                            float inter = __fmul_rn(ih, iw);
                            float uni   = __fsub_rn(__fadd_rn(warea, ar[k]), inter);
                            float i2  = __fadd_rn(inter, inter);
                            float thr = __fmaf_rn(uni, 2.384185791015625e-7f, uni);
                            if (uni > 0.0f && i2 > uni && i2 < thr) {
                                if (__fdiv_rn(inter, uni) > 0.5f) so[k] = ORDNEG;
                            }
                        }
                    }
                }
            }
        } // central while
    } // rounds

    if (rank == 0 && t == 0) {
        int vi = BATCH * 100 * 6 + batch;
        if (vi < out_size) out[vi] = (float)emitted;
    }
    cluster.sync();   // no CTA may exit while peers may still target its DSMEM
}

// smem totals per cluster size
template<int CS> struct SmemTot {
    static constexpr int PER = NANCH / CS;
    static constexpr int v = PER * 16 + 128 + 128 * CS + 16;
};

// ---------------------------------------------------------------------------
extern "C" void kernel_launch(void* const* d_in, const int* in_sizes, int n_in,
                              void* d_out, int out_size)
{
    const float* b20 = (const float*)d_in[0];
    const float* p20 = (const float*)d_in[1];
    const float* c20 = (const float*)d_in[2];
    const float* b40 = (const float*)d_in[3];
    const float* p40 = (const float*)d_in[4];
    const float* c40 = (const float*)d_in[5];
    const float* b80 = (const float*)d_in[6];
    const float* p80 = (const float*)d_in[7];
    const float* c80 = (const float*)d_in[8];
    float* out = (float*)d_out;

    int total = BATCH * NANCH;
    int blocks = (total + TPB - 1) / TPB;
    prep_kernel<<<blocks, TPB>>>(b20, p20, c20, b40, p40, c40, b80, p80, c80, out, out_size);

    // Prefer cluster=16 (non-portable); fall back to 8 if not grantable.
    cudaFuncSetAttribute(nms_kernel<16>, cudaFuncAttributeNonPortableClusterSizeAllowed, 1);
    cudaFuncSetAttribute(nms_kernel<16>, cudaFuncAttributeMaxDynamicSharedMemorySize, SmemTot<16>::v);
    cudaFuncSetAttribute(nms_kernel<8>,  cudaFuncAttributeMaxDynamicSharedMemorySize, SmemTot<8>::v);

    cudaLaunchConfig_t q = {};
    q.gridDim  = dim3(BATCH * 16, 1, 1);
    q.blockDim = dim3(TPB, 1, 1);
    q.dynamicSmemBytes = SmemTot<16>::v;
    q.stream = 0;
    int maxc = 0;
    cudaOccupancyMaxPotentialClusterSize(&maxc, nms_kernel<16>, &q);

    cudaLaunchAttribute at[1];
    at[0].id = cudaLaunchAttributeClusterDimension;

    if (maxc >= 16) {
        cudaLaunchConfig_t cfg = {};
        cfg.gridDim  = dim3(BATCH * 16, 1, 1);
        cfg.blockDim = dim3(TPB, 1, 1);
        cfg.dynamicSmemBytes = SmemTot<16>::v;
        cfg.stream = 0;
        at[0].val.clusterDim = {16, 1, 1};
        cfg.attrs = at; cfg.numAttrs = 1;
        cudaLaunchKernelEx(&cfg, nms_kernel<16>, out, out_size);
    } else {
        cudaLaunchConfig_t cfg = {};
        cfg.gridDim  = dim3(BATCH * 8, 1, 1);
        cfg.blockDim = dim3(TPB, 1, 1);
        cfg.dynamicSmemBytes = SmemTot<8>::v;
        cfg.stream = 0;
        at[0].val.clusterDim = {8, 1, 1};
        cfg.attrs = at; cfg.numAttrs = 1;
        cudaLaunchKernelEx(&cfg, nms_kernel<8>, out, out_size);
    }
}